// round 9
// baseline (speedup 1.0000x reference)
#include <cuda_runtime.h>
#include <math.h>

#define DIMC    512
#define HEADS   8
#define HD      64
#define NTOK    9
#define HIDDIM  2048
#define WPC     2                 // windows per CTA
#define ROWS    (WPC * NTOK)      // 18
#define HROWS   9                 // rows per thread-half
#define THREADS 512
#define XS      516               // row stride (floats) for x/h buffers
#define AS      2052              // row stride (floats) for big qkv/fc1 buffer
#define SMEM_FLOATS (2 * ROWS * XS + ROWS * AS)
#define SMEM_BYTES  (SMEM_FLOATS * 4)     // 222048 B, 1 CTA/SM

// ---------------- packed (k-pair interleaved) weight scratch: Wp[k/2][NOUT][2] ----------------
__device__ __align__(16) float g_wp_qkv [DIMC * 3 * DIMC];
__device__ __align__(16) float g_wp_proj[DIMC * DIMC];
__device__ __align__(16) float g_wp_fc1 [DIMC * HIDDIM];
__device__ __align__(16) float g_wp_fc2 [HIDDIM * DIMC];

#define N_QKV  (3 * DIMC * DIMC)
#define N_PROJ (DIMC * DIMC)
#define N_FC1  (HIDDIM * DIMC)
#define N_FC2  (DIMC * HIDDIM)
#define N_ALL  (N_QKV + N_PROJ + N_FC1 + N_FC2)

__device__ __forceinline__ void pack_one(const float* __restrict__ in, float* __restrict__ out,
                                         int NOUT, int K, int idx) {
    int j = idx / K;
    int k = idx - j * K;
    out[((k >> 1) * NOUT + j) * 2 + (k & 1)] = in[idx];
}

__global__ void pack_all(const float* __restrict__ w_qkv, const float* __restrict__ w_proj,
                         const float* __restrict__ w_fc1, const float* __restrict__ w_fc2) {
    for (int idx = blockIdx.x * blockDim.x + threadIdx.x; idx < N_ALL; idx += gridDim.x * blockDim.x) {
        if (idx < N_QKV)                       pack_one(w_qkv,  g_wp_qkv,  3 * DIMC, DIMC,   idx);
        else if (idx < N_QKV + N_PROJ)         pack_one(w_proj, g_wp_proj, DIMC,     DIMC,   idx - N_QKV);
        else if (idx < N_QKV + N_PROJ + N_FC1) pack_one(w_fc1,  g_wp_fc1,  HIDDIM,   DIMC,   idx - N_QKV - N_PROJ);
        else                                   pack_one(w_fc2,  g_wp_fc2,  DIMC,     HIDDIM, idx - N_QKV - N_PROJ - N_FC1);
    }
}

// ---------------- packed f32x2 FMA (Blackwell FFMA2 — 2 MACs/instr) ----------------
__device__ __forceinline__ void ffma2(unsigned long long& d, unsigned long long a, unsigned long long b) {
    asm("fma.rn.f32x2 %0, %1, %2, %0;" : "+l"(d) : "l"(a), "l"(b));
}
__device__ __forceinline__ float sum2(unsigned long long u) {
    float lo, hi;
    asm("mov.b64 {%0, %1}, %2;" : "=f"(lo), "=f"(hi) : "l"(u));
    return lo + hi;
}
__device__ __forceinline__ float gelu_exact(float v) {
    return 0.5f * v * (1.0f + erff(v * 0.70710678118654752440f));
}

// Half-CTA GEMM: thread handles 2 columns x 9 rows (row-half = tid>>8).
// Wp layout: [K/2][NOUT][2]. INS/OUTS compile-time -> LDS immediates (no ALU).
// MODE 0: store, 1: add into sOut (residual), 2: gelu then store
template<int K, int NOUT, int MODE, int INS, int OUTS>
__device__ __forceinline__ void gemm9(const float* __restrict__ Wp,
                                      const float* __restrict__ bias,
                                      const float* __restrict__ sIn,
                                      float* __restrict__ sOut) {
    const int tid = threadIdx.x;
    const int rh  = tid >> 8;            // row half: 0 or 1
    const int tj  = tid & 255;
    const float* sInr = sIn + rh * HROWS * INS;
    float*       sOutr = sOut + rh * HROWS * OUTS;
    for (int j0 = 2 * tj; j0 < NOUT; j0 += 2 * 256) {
        unsigned long long a0[HROWS], a1[HROWS];
#pragma unroll
        for (int r = 0; r < HROWS; r++) { a0[r] = 0ull; a1[r] = 0ull; }
        const float* wbase = Wp + j0 * 2;
        // prologue: prefetch chunk 0 weights
        ulonglong2 w0 = *(const ulonglong2*)(wbase);
        ulonglong2 w1 = *(const ulonglong2*)(wbase + 2 * NOUT);
#pragma unroll 2
        for (int k = 0; k < K; k += 4) {
            const int kp = (k + 4 < K) ? ((k >> 1) + 2) : 0;   // clamped (L2-hot re-read)
            ulonglong2 nw0 = *(const ulonglong2*)(wbase + (size_t)kp * (2 * NOUT));
            ulonglong2 nw1 = *(const ulonglong2*)(wbase + (size_t)(kp + 1) * (2 * NOUT));
#pragma unroll
            for (int r = 0; r < HROWS; r++) {
                ulonglong2 hv = *(const ulonglong2*)(sInr + r * INS + k);
                ffma2(a0[r], hv.x, w0.x);
                ffma2(a1[r], hv.x, w0.y);
                ffma2(a0[r], hv.y, w1.x);
                ffma2(a1[r], hv.y, w1.y);
            }
            w0 = nw0; w1 = nw1;
        }
        const float b0 = bias[j0], b1 = bias[j0 + 1];
#pragma unroll
        for (int r = 0; r < HROWS; r++) {
            float v0 = sum2(a0[r]) + b0;
            float v1 = sum2(a1[r]) + b1;
            if (MODE == 2) { v0 = gelu_exact(v0); v1 = gelu_exact(v1); }
            float* o = sOutr + r * OUTS + j0;
            if (MODE == 1) { o[0] += v0; o[1] += v1; }
            else           { o[0] = v0;  o[1] = v1;  }
        }
    }
}

__device__ __forceinline__ void layernorm18(const float* __restrict__ in, float* __restrict__ outp,
                                            const float* __restrict__ g, const float* __restrict__ b) {
    const int warp = threadIdx.x >> 5, lane = threadIdx.x & 31;
    for (int r = warp; r < ROWS; r += THREADS / 32) {
        const float* row = in + r * XS;
        float s = 0.f, s2 = 0.f;
#pragma unroll
        for (int c0 = 0; c0 < DIMC; c0 += 128) {
            float4 v = *(const float4*)(row + c0 + lane * 4);
            s  += v.x + v.y + v.z + v.w;
            s2 += v.x * v.x + v.y * v.y + v.z * v.z + v.w * v.w;
        }
#pragma unroll
        for (int o = 16; o > 0; o >>= 1) {
            s  += __shfl_xor_sync(0xffffffffu, s,  o);
            s2 += __shfl_xor_sync(0xffffffffu, s2, o);
        }
        const float mu  = s * (1.f / DIMC);
        const float var = s2 * (1.f / DIMC) - mu * mu;
        const float inv = rsqrtf(var + 1e-5f);
        float* orow = outp + r * XS;
#pragma unroll
        for (int c0 = 0; c0 < DIMC; c0 += 128) {
            const int c = c0 + lane * 4;
            float4 v  = *(const float4*)(row + c);
            float4 gv = *(const float4*)(g + c);
            float4 bv = *(const float4*)(b + c);
            float4 ov;
            ov.x = (v.x - mu) * inv * gv.x + bv.x;
            ov.y = (v.y - mu) * inv * gv.y + bv.y;
            ov.z = (v.z - mu) * inv * gv.z + bv.z;
            ov.w = (v.w - mu) * inv * gv.w + bv.w;
            *(float4*)(orow + c) = ov;
        }
    }
}

__global__ void __launch_bounds__(THREADS, 1)
swin_block_kernel(const float* __restrict__ x,
                  const float* __restrict__ gamma1, const float* __restrict__ beta1,
                  const float* __restrict__ b_qkv,
                  const float* __restrict__ bias_table,
                  const float* __restrict__ b_proj,
                  const float* __restrict__ gamma2, const float* __restrict__ beta2,
                  const float* __restrict__ b_fc1,  const float* __restrict__ b_fc2,
                  const float* __restrict__ w_conv, const float* __restrict__ b_conv,
                  float* __restrict__ out, int nbatch) {
    extern __shared__ float smem[];
    float* bufx = smem;                    // [ROWS][XS] residual / x
    float* bufh = smem + ROWS * XS;        // [ROWS][XS] LN out / attn out
    float* bufa = smem + 2 * ROWS * XS;    // [ROWS][AS] qkv / fc1 hidden
    const int tid  = threadIdx.x;
    const int wid  = tid >> 5, lane = tid & 31;
    const int win0  = blockIdx.x * WPC;
    const int nwin  = (nbatch - win0 < WPC) ? (nbatch - win0) : WPC;
    const int nrows = nwin * NTOK;
    const size_t base = (size_t)win0 * NTOK * DIMC;

    // ---- load x (zero-fill unused rows so GEMMs stay branch-free) ----
    for (int i = tid; i < ROWS * (DIMC / 4); i += THREADS) {
        const int r = i >> 7;              // DIMC/4 = 128
        const int c = (i & 127) << 2;
        float4 v = make_float4(0.f, 0.f, 0.f, 0.f);
        if (r < nrows) v = *(const float4*)(x + base + (size_t)r * DIMC + c);
        *(float4*)(bufx + r * XS + c) = v;
    }
    __syncthreads();

    // ---- LN1 ----
    layernorm18(bufx, bufh, gamma1, beta1);
    __syncthreads();

    // ---- QKV GEMM: bufa[18][1536] ----
    gemm9<DIMC, 3 * DIMC, 0, XS, AS>(g_wp_qkv, b_qkv, bufh, bufa);
    __syncthreads();

    // ---- windowed attention: 16 warps = 8 heads x 2 windows; 9 lanes each ----
    if (lane < NTOK) {
        const int h   = wid & 7;
        const int win = wid >> 3;          // 0 or 1
        const int i   = lane;
        const float* qb = bufa + (win * NTOK + i) * AS + h * HD;
        float4 q[HD / 4];
#pragma unroll
        for (int t = 0; t < HD / 4; t++) q[t] = *(const float4*)(qb + 4 * t);
        float s[NTOK];
        float m = -1e30f;
#pragma unroll
        for (int j = 0; j < NTOK; j++) {
            const float* kb = bufa + (win * NTOK + j) * AS + DIMC + h * HD;
            float acc = 0.f;
#pragma unroll
            for (int t = 0; t < HD / 4; t++) {
                const float4 kv = *(const float4*)(kb + 4 * t);
                acc += q[t].x * kv.x + q[t].y * kv.y + q[t].z * kv.z + q[t].w * kv.w;
            }
            const int ri = i / 3, ci = i - ri * 3;
            const int rj = j / 3, cj = j - rj * 3;
            const int bidx = (ri - rj + 2) * 5 + (ci - cj + 2);
            s[j] = acc * 0.125f + __ldg(bias_table + bidx * HEADS + h);
            m = fmaxf(m, s[j]);
        }
        float sum = 0.f;
#pragma unroll
        for (int j = 0; j < NTOK; j++) { s[j] = expf(s[j] - m); sum += s[j]; }
        const float inv = 1.f / sum;
        float* ob = bufh + (win * NTOK + i) * XS + h * HD;
#pragma unroll
        for (int t = 0; t < HD / 4; t++) {
            float4 o = make_float4(0.f, 0.f, 0.f, 0.f);
#pragma unroll
            for (int j = 0; j < NTOK; j++) {
                const float4 vv = *(const float4*)(bufa + (win * NTOK + j) * AS + 2 * DIMC + h * HD + 4 * t);
                o.x += s[j] * vv.x; o.y += s[j] * vv.y;
                o.z += s[j] * vv.z; o.w += s[j] * vv.w;
            }
            o.x *= inv; o.y *= inv; o.z *= inv; o.w *= inv;
            *(float4*)(ob + 4 * t) = o;
        }
    }
    __syncthreads();

    // ---- proj GEMM + residual into bufx ----
    gemm9<DIMC, DIMC, 1, XS, XS>(g_wp_proj, b_proj, bufh, bufx);
    __syncthreads();

    // ---- LN2 ----
    layernorm18(bufx, bufh, gamma2, beta2);
    __syncthreads();

    // ---- fc1 + GELU: bufa[18][2048] ----
    gemm9<DIMC, HIDDIM, 2, XS, AS>(g_wp_fc1, b_fc1, bufh, bufa);
    __syncthreads();

    // ---- fc2 + residual into bufx ----
    gemm9<HIDDIM, DIMC, 1, AS, XS>(g_wp_fc2, b_fc2, bufa, bufx);
    __syncthreads();

    // ---- depthwise 3x3 "valid" conv => per-window reduce over 9 tokens ----
#pragma unroll
    for (int w = 0; w < WPC; w++) {
        if (w >= nwin) break;
        for (int c = tid; c < DIMC; c += THREADS) {
            float acc = b_conv[c];
#pragma unroll
            for (int n = 0; n < NTOK; n++)
                acc = fmaf(bufx[(w * NTOK + n) * XS + c], __ldg(w_conv + c * NTOK + n), acc);
            out[((size_t)win0 + w) * DIMC + c] = acc;
        }
    }
}

extern "C" void kernel_launch(void* const* d_in, const int* in_sizes, int n_in,
                              void* d_out, int out_size) {
    const float* x          = (const float*)d_in[0];
    const float* gamma1     = (const float*)d_in[1];
    const float* beta1      = (const float*)d_in[2];
    const float* w_qkv      = (const float*)d_in[3];
    const float* b_qkv      = (const float*)d_in[4];
    const float* bias_table = (const float*)d_in[5];
    const float* w_proj     = (const float*)d_in[6];
    const float* b_proj     = (const float*)d_in[7];
    const float* gamma2     = (const float*)d_in[8];
    const float* beta2      = (const float*)d_in[9];
    const float* w_fc1      = (const float*)d_in[10];
    const float* b_fc1      = (const float*)d_in[11];
    const float* w_fc2      = (const float*)d_in[12];
    const float* b_fc2      = (const float*)d_in[13];
    const float* w_conv     = (const float*)d_in[14];
    const float* b_conv     = (const float*)d_in[15];
    float* out = (float*)d_out;

    const int nbatch = in_sizes[0] / (NTOK * DIMC);
    const int grid   = (nbatch + WPC - 1) / WPC;

    pack_all<<<2048, 256>>>(w_qkv, w_proj, w_fc1, w_fc2);

    cudaFuncSetAttribute(swin_block_kernel, cudaFuncAttributeMaxDynamicSharedMemorySize, SMEM_BYTES);
    swin_block_kernel<<<grid, THREADS, SMEM_BYTES>>>(
        x, gamma1, beta1, b_qkv, bias_table, b_proj, gamma2, beta2,
        b_fc1, b_fc2, w_conv, b_conv, out, nbatch);
}

// round 10
// speedup vs baseline: 1.6113x; 1.6113x over previous
#include <cuda_runtime.h>
#include <math.h>

#define DIMC    512
#define HEADS   8
#define HD      64
#define NTOK    9
#define HIDDIM  2048
#define WPC     1                 // windows per CTA (1 -> 111KB smem -> 2 CTAs/SM)
#define ROWS    (WPC * NTOK)      // 9
#define THREADS 256
#define XS      516               // row stride (floats) for x/h buffers
#define AS      2052              // row stride (floats) for qkv/fc1 buffer
#define SMEM_FLOATS (2 * ROWS * XS + ROWS * AS)
#define SMEM_BYTES  (SMEM_FLOATS * 4)     // 111024 B -> 2 CTAs/SM

// ---------------- packed (k-pair interleaved) weight scratch: Wp[k/2][NOUT][2] ----------------
__device__ __align__(16) float g_wp_qkv [DIMC * 3 * DIMC];
__device__ __align__(16) float g_wp_proj[DIMC * DIMC];
__device__ __align__(16) float g_wp_fc1 [DIMC * HIDDIM];
__device__ __align__(16) float g_wp_fc2 [HIDDIM * DIMC];

#define N_QKV  (3 * DIMC * DIMC)
#define N_PROJ (DIMC * DIMC)
#define N_FC1  (HIDDIM * DIMC)
#define N_FC2  (DIMC * HIDDIM)
#define N_ALL  (N_QKV + N_PROJ + N_FC1 + N_FC2)

__device__ __forceinline__ void pack_one(const float* __restrict__ in, float* __restrict__ out,
                                         int NOUT, int K, int idx) {
    int j = idx / K;
    int k = idx - j * K;
    out[((k >> 1) * NOUT + j) * 2 + (k & 1)] = in[idx];
}

__global__ void pack_all(const float* __restrict__ w_qkv, const float* __restrict__ w_proj,
                         const float* __restrict__ w_fc1, const float* __restrict__ w_fc2) {
    for (int idx = blockIdx.x * blockDim.x + threadIdx.x; idx < N_ALL; idx += gridDim.x * blockDim.x) {
        if (idx < N_QKV)                       pack_one(w_qkv,  g_wp_qkv,  3 * DIMC, DIMC,   idx);
        else if (idx < N_QKV + N_PROJ)         pack_one(w_proj, g_wp_proj, DIMC,     DIMC,   idx - N_QKV);
        else if (idx < N_QKV + N_PROJ + N_FC1) pack_one(w_fc1,  g_wp_fc1,  HIDDIM,   DIMC,   idx - N_QKV - N_PROJ);
        else                                   pack_one(w_fc2,  g_wp_fc2,  DIMC,     HIDDIM, idx - N_QKV - N_PROJ - N_FC1);
    }
}

// ---------------- packed f32x2 FMA (Blackwell FFMA2 — 2 MACs/instr) ----------------
__device__ __forceinline__ void ffma2(unsigned long long& d, unsigned long long a, unsigned long long b) {
    asm("fma.rn.f32x2 %0, %1, %2, %0;" : "+l"(d) : "l"(a), "l"(b));
}
__device__ __forceinline__ float sum2(unsigned long long u) {
    float lo, hi;
    asm("mov.b64 {%0, %1}, %2;" : "=f"(lo), "=f"(hi) : "l"(u));
    return lo + hi;
}
__device__ __forceinline__ float gelu_exact(float v) {
    return 0.5f * v * (1.0f + erff(v * 0.70710678118654752440f));
}

// out[r][j] = epilogue( sum_k in[r][k] * W[j][k] + bias[j] ), 9 rows, 2 cols/thread.
// Wp layout: [K/2][NOUT][2]. INS/OUTS compile-time -> address math folds to immediates.
// MODE 0: store, 1: add into sOut (residual), 2: gelu then store
template<int K, int NOUT, int MODE, int INS, int OUTS>
__device__ __forceinline__ void gemm9(const float* __restrict__ Wp,
                                      const float* __restrict__ bias,
                                      const float* __restrict__ sIn,
                                      float* __restrict__ sOut) {
    const int tid = threadIdx.x;
    for (int j0 = 2 * tid; j0 < NOUT; j0 += 2 * THREADS) {
        unsigned long long a0[ROWS], a1[ROWS];
#pragma unroll
        for (int r = 0; r < ROWS; r++) { a0[r] = 0ull; a1[r] = 0ull; }
        const float* wbase = Wp + j0 * 2;
        // prologue: prefetch chunk 0 weights (distance-1 pipeline)
        ulonglong2 w0 = *(const ulonglong2*)(wbase);
        ulonglong2 w1 = *(const ulonglong2*)(wbase + 2 * NOUT);
#pragma unroll 2
        for (int k = 0; k < K; k += 4) {
            const int kp = (k + 4 < K) ? ((k >> 1) + 2) : 0;   // clamped (L2-hot re-read)
            ulonglong2 nw0 = *(const ulonglong2*)(wbase + (size_t)kp * (2 * NOUT));
            ulonglong2 nw1 = *(const ulonglong2*)(wbase + (size_t)(kp + 1) * (2 * NOUT));
#pragma unroll
            for (int r = 0; r < ROWS; r++) {
                ulonglong2 hv = *(const ulonglong2*)(sIn + r * INS + k);
                ffma2(a0[r], hv.x, w0.x);
                ffma2(a1[r], hv.x, w0.y);
                ffma2(a0[r], hv.y, w1.x);
                ffma2(a1[r], hv.y, w1.y);
            }
            w0 = nw0; w1 = nw1;
        }
        const float b0 = bias[j0], b1 = bias[j0 + 1];
#pragma unroll
        for (int r = 0; r < ROWS; r++) {
            float v0 = sum2(a0[r]) + b0;
            float v1 = sum2(a1[r]) + b1;
            if (MODE == 2) { v0 = gelu_exact(v0); v1 = gelu_exact(v1); }
            float* o = sOut + r * OUTS + j0;
            if (MODE == 1) { o[0] += v0; o[1] += v1; }
            else           { o[0] = v0;  o[1] = v1;  }
        }
    }
}

__device__ __forceinline__ void layernorm9(const float* __restrict__ in, float* __restrict__ outp,
                                           const float* __restrict__ g, const float* __restrict__ b) {
    const int warp = threadIdx.x >> 5, lane = threadIdx.x & 31;
    for (int r = warp; r < ROWS; r += THREADS / 32) {
        const float* row = in + r * XS;
        float s = 0.f, s2 = 0.f;
#pragma unroll
        for (int c0 = 0; c0 < DIMC; c0 += 128) {
            float4 v = *(const float4*)(row + c0 + lane * 4);
            s  += v.x + v.y + v.z + v.w;
            s2 += v.x * v.x + v.y * v.y + v.z * v.z + v.w * v.w;
        }
#pragma unroll
        for (int o = 16; o > 0; o >>= 1) {
            s  += __shfl_xor_sync(0xffffffffu, s,  o);
            s2 += __shfl_xor_sync(0xffffffffu, s2, o);
        }
        const float mu  = s * (1.f / DIMC);
        const float var = s2 * (1.f / DIMC) - mu * mu;
        const float inv = rsqrtf(var + 1e-5f);
        float* orow = outp + r * XS;
#pragma unroll
        for (int c0 = 0; c0 < DIMC; c0 += 128) {
            const int c = c0 + lane * 4;
            float4 v  = *(const float4*)(row + c);
            float4 gv = *(const float4*)(g + c);
            float4 bv = *(const float4*)(b + c);
            float4 ov;
            ov.x = (v.x - mu) * inv * gv.x + bv.x;
            ov.y = (v.y - mu) * inv * gv.y + bv.y;
            ov.z = (v.z - mu) * inv * gv.z + bv.z;
            ov.w = (v.w - mu) * inv * gv.w + bv.w;
            *(float4*)(orow + c) = ov;
        }
    }
}

__global__ void __launch_bounds__(THREADS, 2)
swin_block_kernel(const float* __restrict__ x,
                  const float* __restrict__ gamma1, const float* __restrict__ beta1,
                  const float* __restrict__ b_qkv,
                  const float* __restrict__ bias_table,
                  const float* __restrict__ b_proj,
                  const float* __restrict__ gamma2, const float* __restrict__ beta2,
                  const float* __restrict__ b_fc1,  const float* __restrict__ b_fc2,
                  const float* __restrict__ w_conv, const float* __restrict__ b_conv,
                  float* __restrict__ out, int nbatch) {
    extern __shared__ float smem[];
    float* bufx = smem;                    // [9][XS] residual / x
    float* bufh = smem + ROWS * XS;        // [9][XS] LN out / attn out
    float* bufa = smem + 2 * ROWS * XS;    // [9][AS] qkv / fc1 hidden
    const int tid  = threadIdx.x;
    const int wid  = tid >> 5, lane = tid & 31;
    const int win  = blockIdx.x;           // one window per CTA
    const size_t base = (size_t)win * NTOK * DIMC;

    // ---- load x ----
    for (int i = tid; i < ROWS * (DIMC / 4); i += THREADS) {
        const int r = i >> 7;              // DIMC/4 = 128
        const int c = (i & 127) << 2;
        *(float4*)(bufx + r * XS + c) = *(const float4*)(x + base + (size_t)r * DIMC + c);
    }
    __syncthreads();

    // ---- LN1 ----
    layernorm9(bufx, bufh, gamma1, beta1);
    __syncthreads();

    // ---- QKV GEMM: bufa[9][1536] ----
    gemm9<DIMC, 3 * DIMC, 0, XS, AS>(g_wp_qkv, b_qkv, bufh, bufa);
    __syncthreads();

    // ---- windowed attention: 8 warps = 8 heads; 9 lanes each ----
    if (lane < NTOK) {
        const int h = wid;
        const int i = lane;
        const float* qb = bufa + i * AS + h * HD;
        float4 q[HD / 4];
#pragma unroll
        for (int t = 0; t < HD / 4; t++) q[t] = *(const float4*)(qb + 4 * t);
        float s[NTOK];
        float m = -1e30f;
#pragma unroll
        for (int j = 0; j < NTOK; j++) {
            const float* kb = bufa + j * AS + DIMC + h * HD;
            float acc = 0.f;
#pragma unroll
            for (int t = 0; t < HD / 4; t++) {
                const float4 kv = *(const float4*)(kb + 4 * t);
                acc += q[t].x * kv.x + q[t].y * kv.y + q[t].z * kv.z + q[t].w * kv.w;
            }
            const int ri = i / 3, ci = i - ri * 3;
            const int rj = j / 3, cj = j - rj * 3;
            const int bidx = (ri - rj + 2) * 5 + (ci - cj + 2);
            s[j] = acc * 0.125f + __ldg(bias_table + bidx * HEADS + h);
            m = fmaxf(m, s[j]);
        }
        float sum = 0.f;
#pragma unroll
        for (int j = 0; j < NTOK; j++) { s[j] = expf(s[j] - m); sum += s[j]; }
        const float inv = 1.f / sum;
        float* ob = bufh + i * XS + h * HD;
#pragma unroll
        for (int t = 0; t < HD / 4; t++) {
            float4 o = make_float4(0.f, 0.f, 0.f, 0.f);
#pragma unroll
            for (int j = 0; j < NTOK; j++) {
                const float4 vv = *(const float4*)(bufa + j * AS + 2 * DIMC + h * HD + 4 * t);
                o.x += s[j] * vv.x; o.y += s[j] * vv.y;
                o.z += s[j] * vv.z; o.w += s[j] * vv.w;
            }
            o.x *= inv; o.y *= inv; o.z *= inv; o.w *= inv;
            *(float4*)(ob + 4 * t) = o;
        }
    }
    __syncthreads();

    // ---- proj GEMM + residual into bufx ----
    gemm9<DIMC, DIMC, 1, XS, XS>(g_wp_proj, b_proj, bufh, bufx);
    __syncthreads();

    // ---- LN2 ----
    layernorm9(bufx, bufh, gamma2, beta2);
    __syncthreads();

    // ---- fc1 + GELU: bufa[9][2048] ----
    gemm9<DIMC, HIDDIM, 2, XS, AS>(g_wp_fc1, b_fc1, bufh, bufa);
    __syncthreads();

    // ---- fc2 + residual into bufx ----
    gemm9<HIDDIM, DIMC, 1, AS, XS>(g_wp_fc2, b_fc2, bufa, bufx);
    __syncthreads();

    // ---- depthwise 3x3 "valid" conv => per-window reduce over 9 tokens ----
    for (int c = tid; c < DIMC; c += THREADS) {
        float acc = b_conv[c];
#pragma unroll
        for (int n = 0; n < NTOK; n++)
            acc = fmaf(bufx[n * XS + c], __ldg(w_conv + c * NTOK + n), acc);
        out[(size_t)win * DIMC + c] = acc;
    }
}

extern "C" void kernel_launch(void* const* d_in, const int* in_sizes, int n_in,
                              void* d_out, int out_size) {
    const float* x          = (const float*)d_in[0];
    const float* gamma1     = (const float*)d_in[1];
    const float* beta1      = (const float*)d_in[2];
    const float* w_qkv      = (const float*)d_in[3];
    const float* b_qkv      = (const float*)d_in[4];
    const float* bias_table = (const float*)d_in[5];
    const float* w_proj     = (const float*)d_in[6];
    const float* b_proj     = (const float*)d_in[7];
    const float* gamma2     = (const float*)d_in[8];
    const float* beta2      = (const float*)d_in[9];
    const float* w_fc1      = (const float*)d_in[10];
    const float* b_fc1      = (const float*)d_in[11];
    const float* w_fc2      = (const float*)d_in[12];
    const float* b_fc2      = (const float*)d_in[13];
    const float* w_conv     = (const float*)d_in[14];
    const float* b_conv     = (const float*)d_in[15];
    float* out = (float*)d_out;

    const int nbatch = in_sizes[0] / (NTOK * DIMC);

    pack_all<<<2048, 256>>>(w_qkv, w_proj, w_fc1, w_fc2);

    cudaFuncSetAttribute(swin_block_kernel, cudaFuncAttributeMaxDynamicSharedMemorySize, SMEM_BYTES);
    swin_block_kernel<<<nbatch, THREADS, SMEM_BYTES>>>(
        x, gamma1, beta1, b_qkv, bias_table, b_proj, gamma2, beta2,
        b_fc1, b_fc2, w_conv, b_conv, out, nbatch);
}

// round 14
// speedup vs baseline: 1.6217x; 1.0065x over previous
#include <cuda_runtime.h>
#include <math.h>

#define DIMC    512
#define HEADS   8
#define HD      64
#define NTOK    9
#define HIDDIM  2048
#define WPC     2                 // windows per CTA (18-row weight reuse)
#define ROWS    (WPC * NTOK)      // 18
#define THREADS 384               // 12 warps = 3/SMSP; 384*~164 regs < 64K RF, no spill
#define XS      516               // row stride (floats) for x/h buffers
#define AS      2052              // row stride (floats) for qkv/fc1 buffer
#define SMEM_FLOATS (2 * ROWS * XS + ROWS * AS)
#define SMEM_BYTES  (SMEM_FLOATS * 4)     // 222048 B -> 1 CTA/SM

// ---------------- packed (k-pair interleaved) weight scratch: Wp[k/2][NOUT][2] ----------------
__device__ __align__(16) float g_wp_qkv [DIMC * 3 * DIMC];
__device__ __align__(16) float g_wp_proj[DIMC * DIMC];
__device__ __align__(16) float g_wp_fc1 [DIMC * HIDDIM];
__device__ __align__(16) float g_wp_fc2 [HIDDIM * DIMC];

#define N_QKV  (3 * DIMC * DIMC)
#define N_PROJ (DIMC * DIMC)
#define N_FC1  (HIDDIM * DIMC)
#define N_FC2  (DIMC * HIDDIM)
#define N_ALL  (N_QKV + N_PROJ + N_FC1 + N_FC2)

__device__ __forceinline__ void pack_one(const float* __restrict__ in, float* __restrict__ out,
                                         int NOUT, int K, int idx) {
    int j = idx / K;
    int k = idx - j * K;
    out[((k >> 1) * NOUT + j) * 2 + (k & 1)] = in[idx];
}

__global__ void pack_all(const float* __restrict__ w_qkv, const float* __restrict__ w_proj,
                         const float* __restrict__ w_fc1, const float* __restrict__ w_fc2) {
    for (int idx = blockIdx.x * blockDim.x + threadIdx.x; idx < N_ALL; idx += gridDim.x * blockDim.x) {
        if (idx < N_QKV)                       pack_one(w_qkv,  g_wp_qkv,  3 * DIMC, DIMC,   idx);
        else if (idx < N_QKV + N_PROJ)         pack_one(w_proj, g_wp_proj, DIMC,     DIMC,   idx - N_QKV);
        else if (idx < N_QKV + N_PROJ + N_FC1) pack_one(w_fc1,  g_wp_fc1,  HIDDIM,   DIMC,   idx - N_QKV - N_PROJ);
        else                                   pack_one(w_fc2,  g_wp_fc2,  DIMC,     HIDDIM, idx - N_QKV - N_PROJ - N_FC1);
    }
}

// ---------------- packed f32x2 FMA (Blackwell FFMA2 — 2 MACs/instr) ----------------
__device__ __forceinline__ void ffma2(unsigned long long& d, unsigned long long a, unsigned long long b) {
    asm("fma.rn.f32x2 %0, %1, %2, %0;" : "+l"(d) : "l"(a), "l"(b));
}
__device__ __forceinline__ float sum2(unsigned long long u) {
    float lo, hi;
    asm("mov.b64 {%0, %1}, %2;" : "=f"(lo), "=f"(hi) : "l"(u));
    return lo + hi;
}
__device__ __forceinline__ float gelu_exact(float v) {
    return 0.5f * v * (1.0f + erff(v * 0.70710678118654752440f));
}

// out[r][j] = epilogue( sum_k in[r][k] * W[j][k] + bias[j] ), 18 rows, 2 cols/thread.
// Wp layout: [K/2][NOUT][2]. INS/OUTS compile-time -> address math folds to immediates.
// MODE 0: store, 1: add into sOut (residual), 2: gelu then store
template<int K, int NOUT, int MODE, int INS, int OUTS>
__device__ __forceinline__ void gemm18(const float* __restrict__ Wp,
                                       const float* __restrict__ bias,
                                       const float* __restrict__ sIn,
                                       float* __restrict__ sOut) {
    const int tid = threadIdx.x;
    for (int j0 = 2 * tid; j0 < NOUT; j0 += 2 * THREADS) {
        unsigned long long a0[ROWS], a1[ROWS];
#pragma unroll
        for (int r = 0; r < ROWS; r++) { a0[r] = 0ull; a1[r] = 0ull; }
        const float* wbase = Wp + j0 * 2;
        // prologue: prefetch chunk 0 weights (distance-1 pipeline)
        ulonglong2 w0 = *(const ulonglong2*)(wbase);
        ulonglong2 w1 = *(const ulonglong2*)(wbase + 2 * NOUT);
#pragma unroll 2
        for (int k = 0; k < K; k += 4) {
            const int kp = (k + 4 < K) ? ((k >> 1) + 2) : 0;   // clamped (L2-hot re-read)
            ulonglong2 nw0 = *(const ulonglong2*)(wbase + (size_t)kp * (2 * NOUT));
            ulonglong2 nw1 = *(const ulonglong2*)(wbase + (size_t)(kp + 1) * (2 * NOUT));
#pragma unroll
            for (int r = 0; r < ROWS; r++) {
                ulonglong2 hv = *(const ulonglong2*)(sIn + r * INS + k);
                ffma2(a0[r], hv.x, w0.x);
                ffma2(a1[r], hv.x, w0.y);
                ffma2(a0[r], hv.y, w1.x);
                ffma2(a1[r], hv.y, w1.y);
            }
            w0 = nw0; w1 = nw1;
        }
        const float b0 = bias[j0], b1 = bias[j0 + 1];
#pragma unroll
        for (int r = 0; r < ROWS; r++) {
            float v0 = sum2(a0[r]) + b0;
            float v1 = sum2(a1[r]) + b1;
            if (MODE == 2) { v0 = gelu_exact(v0); v1 = gelu_exact(v1); }
            float* o = sOut + r * OUTS + j0;
            if (MODE == 1) { o[0] += v0; o[1] += v1; }
            else           { o[0] = v0;  o[1] = v1;  }
        }
    }
}

__device__ __forceinline__ void layernorm18(const float* __restrict__ in, float* __restrict__ outp,
                                            const float* __restrict__ g, const float* __restrict__ b) {
    const int warp = threadIdx.x >> 5, lane = threadIdx.x & 31;
    for (int r = warp; r < ROWS; r += THREADS / 32) {
        const float* row = in + r * XS;
        float s = 0.f, s2 = 0.f;
#pragma unroll
        for (int c0 = 0; c0 < DIMC; c0 += 128) {
            float4 v = *(const float4*)(row + c0 + lane * 4);
            s  += v.x + v.y + v.z + v.w;
            s2 += v.x * v.x + v.y * v.y + v.z * v.z + v.w * v.w;
        }
#pragma unroll
        for (int o = 16; o > 0; o >>= 1) {
            s  += __shfl_xor_sync(0xffffffffu, s,  o);
            s2 += __shfl_xor_sync(0xffffffffu, s2, o);
        }
        const float mu  = s * (1.f / DIMC);
        const float var = s2 * (1.f / DIMC) - mu * mu;
        const float inv = rsqrtf(var + 1e-5f);
        float* orow = outp + r * XS;
#pragma unroll
        for (int c0 = 0; c0 < DIMC; c0 += 128) {
            const int c = c0 + lane * 4;
            float4 v  = *(const float4*)(row + c);
            float4 gv = *(const float4*)(g + c);
            float4 bv = *(const float4*)(b + c);
            float4 ov;
            ov.x = (v.x - mu) * inv * gv.x + bv.x;
            ov.y = (v.y - mu) * inv * gv.y + bv.y;
            ov.z = (v.z - mu) * inv * gv.z + bv.z;
            ov.w = (v.w - mu) * inv * gv.w + bv.w;
            *(float4*)(orow + c) = ov;
        }
    }
}

__global__ void __launch_bounds__(THREADS, 1)
swin_block_kernel(const float* __restrict__ x,
                  const float* __restrict__ gamma1, const float* __restrict__ beta1,
                  const float* __restrict__ b_qkv,
                  const float* __restrict__ bias_table,
                  const float* __restrict__ b_proj,
                  const float* __restrict__ gamma2, const float* __restrict__ beta2,
                  const float* __restrict__ b_fc1,  const float* __restrict__ b_fc2,
                  const float* __restrict__ w_conv, const float* __restrict__ b_conv,
                  float* __restrict__ out, int nbatch) {
    extern __shared__ float smem[];
    float* bufx = smem;                    // [18][XS] residual / x
    float* bufh = smem + ROWS * XS;        // [18][XS] LN out / attn out
    float* bufa = smem + 2 * ROWS * XS;    // [18][AS] qkv / fc1 hidden
    const int tid  = threadIdx.x;
    const int wid  = tid >> 5, lane = tid & 31;
    const int win0  = blockIdx.x * WPC;
    const int nwin  = (nbatch - win0 < WPC) ? (nbatch - win0) : WPC;
    const int nrows = nwin * NTOK;
    const size_t base = (size_t)win0 * NTOK * DIMC;

    // ---- load x (zero-fill unused rows so GEMMs stay branch-free) ----
    for (int i = tid; i < ROWS * (DIMC / 4); i += THREADS) {
        const int r = i >> 7;              // DIMC/4 = 128
        const int c = (i & 127) << 2;
        float4 v = make_float4(0.f, 0.f, 0.f, 0.f);
        if (r < nrows) v = *(const float4*)(x + base + (size_t)r * DIMC + c);
        *(float4*)(bufx + r * XS + c) = v;
    }
    __syncthreads();

    // ---- LN1 ----
    layernorm18(bufx, bufh, gamma1, beta1);
    __syncthreads();

    // ---- QKV GEMM: bufa[18][1536] ----
    gemm18<DIMC, 3 * DIMC, 0, XS, AS>(g_wp_qkv, b_qkv, bufh, bufa);
    __syncthreads();

    // ---- windowed attention: 8 warps = 8 heads; 18 lanes = 2 windows x 9 tokens ----
    if (wid < HEADS && lane < 2 * NTOK) {
        const int h   = wid;
        const int win = lane / NTOK;       // 0 or 1
        const int i   = lane - win * NTOK;
        const float* qb = bufa + (win * NTOK + i) * AS + h * HD;
        float4 q[HD / 4];
#pragma unroll
        for (int t = 0; t < HD / 4; t++) q[t] = *(const float4*)(qb + 4 * t);
        float s[NTOK];
        float m = -1e30f;
#pragma unroll
        for (int j = 0; j < NTOK; j++) {
            const float* kb = bufa + (win * NTOK + j) * AS + DIMC + h * HD;
            float acc = 0.f;
#pragma unroll
            for (int t = 0; t < HD / 4; t++) {
                const float4 kv = *(const float4*)(kb + 4 * t);
                acc += q[t].x * kv.x + q[t].y * kv.y + q[t].z * kv.z + q[t].w * kv.w;
            }
            const int ri = i / 3, ci = i - ri * 3;
            const int rj = j / 3, cj = j - rj * 3;
            const int bidx = (ri - rj + 2) * 5 + (ci - cj + 2);
            s[j] = acc * 0.125f + __ldg(bias_table + bidx * HEADS + h);
            m = fmaxf(m, s[j]);
        }
        float sum = 0.f;
#pragma unroll
        for (int j = 0; j < NTOK; j++) { s[j] = expf(s[j] - m); sum += s[j]; }
        const float inv = 1.f / sum;
        float* ob = bufh + (win * NTOK + i) * XS + h * HD;
#pragma unroll
        for (int t = 0; t < HD / 4; t++) {
            float4 o = make_float4(0.f, 0.f, 0.f, 0.f);
#pragma unroll
            for (int j = 0; j < NTOK; j++) {
                const float4 vv = *(const float4*)(bufa + (win * NTOK + j) * AS + 2 * DIMC + h * HD + 4 * t);
                o.x += s[j] * vv.x; o.y += s[j] * vv.y;
                o.z += s[j] * vv.z; o.w += s[j] * vv.w;
            }
            o.x *= inv; o.y *= inv; o.z *= inv; o.w *= inv;
            *(float4*)(ob + 4 * t) = o;
        }
    }
    __syncthreads();

    // ---- proj GEMM + residual into bufx ----
    gemm18<DIMC, DIMC, 1, XS, XS>(g_wp_proj, b_proj, bufh, bufx);
    __syncthreads();

    // ---- LN2 ----
    layernorm18(bufx, bufh, gamma2, beta2);
    __syncthreads();

    // ---- fc1 + GELU: bufa[18][2048] ----
    gemm18<DIMC, HIDDIM, 2, XS, AS>(g_wp_fc1, b_fc1, bufh, bufa);
    __syncthreads();

    // ---- fc2 + residual into bufx ----
    gemm18<HIDDIM, DIMC, 1, AS, XS>(g_wp_fc2, b_fc2, bufa, bufx);
    __syncthreads();

    // ---- depthwise 3x3 "valid" conv => per-window reduce over 9 tokens ----
#pragma unroll
    for (int w = 0; w < WPC; w++) {
        if (w >= nwin) break;
        for (int c = tid; c < DIMC; c += THREADS) {
            float acc = b_conv[c];
#pragma unroll
            for (int n = 0; n < NTOK; n++)
                acc = fmaf(bufx[(w * NTOK + n) * XS + c], __ldg(w_conv + c * NTOK + n), acc);
            out[((size_t)win0 + w) * DIMC + c] = acc;
        }
    }
}

extern "C" void kernel_launch(void* const* d_in, const int* in_sizes, int n_in,
                              void* d_out, int out_size) {
    const float* x          = (const float*)d_in[0];
    const float* gamma1     = (const float*)d_in[1];
    const float* beta1      = (const float*)d_in[2];
    const float* w_qkv      = (const float*)d_in[3];
    const float* b_qkv      = (const float*)d_in[4];
    const float* bias_table = (const float*)d_in[5];
    const float* w_proj     = (const float*)d_in[6];
    const float* b_proj     = (const float*)d_in[7];
    const float* gamma2     = (const float*)d_in[8];
    const float* beta2      = (const float*)d_in[9];
    const float* w_fc1      = (const float*)d_in[10];
    const float* b_fc1      = (const float*)d_in[11];
    const float* w_fc2      = (const float*)d_in[12];
    const float* b_fc2      = (const float*)d_in[13];
    const float* w_conv     = (const float*)d_in[14];
    const float* b_conv     = (const float*)d_in[15];
    float* out = (float*)d_out;

    const int nbatch = in_sizes[0] / (NTOK * DIMC);
    const int grid   = (nbatch + WPC - 1) / WPC;

    pack_all<<<2048, 256>>>(w_qkv, w_proj, w_fc1, w_fc2);

    cudaFuncSetAttribute(swin_block_kernel, cudaFuncAttributeMaxDynamicSharedMemorySize, SMEM_BYTES);
    swin_block_kernel<<<grid, THREADS, SMEM_BYTES>>>(
        x, gamma1, beta1, b_qkv, bias_table, b_proj, gamma2, beta2,
        b_fc1, b_fc2, w_conv, b_conv, out, nbatch);
}